// round 7
// baseline (speedup 1.0000x reference)
#include <cuda_runtime.h>
#include <cuda_bf16.h>

#define JT    64
#define IT    512
#define NTHR  128
#define RPT   (IT / NTHR)   // 4 rows per thread
#define MAXB  4096

__device__ double        g_partials[MAXB];
__device__ unsigned int  g_ticket = 0;

typedef unsigned long long u64;

// Monotone order-preserving key for finite floats.
__device__ __forceinline__ unsigned int fkey(float f) {
    int i = __float_as_int(f);
    return (i >= 0) ? ((unsigned)i | 0x80000000u) : ~(unsigned)i;
}

// Exact per-pair loss (slow path): t1 = 0.2s - d, t2 = d - s, u = -d.
__device__ __forceinline__ float sel_loss(float t1, float t2, float u) {
    float mm = fmaxf(t1, t2);
    float s  = (u > 0.0f) ? u : mm;
    return fmaxf(s, 0.0f);
}

__global__ void __launch_bounds__(NTHR, 8)
dl_fused_kernel(const float* __restrict__ p,
                const float* __restrict__ z_spacing,
                const float* __restrict__ nth_slice,
                float* __restrict__ out,
                int n, int nblocks) {
    __shared__ float    sx[JT], sy[JT], sz[JT];   // slow-path per-j precompute
    __shared__ u64      kraw[JT];                 // unsorted keys
    __shared__ unsigned skey[JT];                 // sorted 32-bit value-keys
    __shared__ int      skid[JT];                 // sorted local j index
    __shared__ int      pre[JT + 1];              // prefix sums of skid
    __shared__ float    s_minv;                   // min p_j in tile
    __shared__ double   s_sp[2];                  // partial sums of p_j (double)
    __shared__ int      s_w0;                     // warp-0 scan total
    __shared__ double   wsum[NTHR / 32];
    __shared__ bool     is_last;

    const int tid = threadIdx.x;

    // Decode (ti, tj): per-ti block count = 8*(ti+1), start(ti) = 4*ti*(ti+1).
    int t  = blockIdx.x;
    int ti = (int)((sqrtf((float)t + 1.0f) - 1.0f) * 0.5f);
    while (4 * (ti + 1) * (ti + 2) <= t) ti++;
    while (4 * ti * (ti + 1) > t) ti--;
    const int tj = t - 4 * ti * (ti + 1);

    const float step = z_spacing[0] * nth_slice[0];   // STEP == 1.0
    const float c02  = 0.2f * step;

    const int gj0 = tj * JT;
    const int gi0 = ti * IT + tid;
    const bool fulltile = (gj0 + JT <= n);

    // ---- Stage j-tile (one j per thread, tid < 64) ----
    if (tid < JT) {
        int j = gj0 + tid;
        float pv = (j < n) ? p[j] : 3.0e38f;   // OOR sorts last, never touched
        float jf = (float)j;
        sx[tid] = pv - c02 * jf;
        sy[tid] = step * jf - pv;
        sz[tid] = pv;
        kraw[tid] = ((u64)fkey(pv) << 6) | (u64)tid;
    }

    // Row values (load early, overlap with barriers).
    float pis[RPT];
    int   gis[RPT];
    #pragma unroll
    for (int r = 0; r < RPT; ++r) {
        gis[r] = gi0 + r * NTHR;
        pis[r] = (gis[r] < n) ? p[gis[r]] : 0.0f;
    }

    __syncthreads();

    // ---- Rank sort (tid < 64): rank = #{m: key_m < key_tid} ----
    if (tid < JT) {
        u64 mykey = kraw[tid];
        int r = 0;
        #pragma unroll 8
        for (int m = 0; m < JT; ++m)
            r += (kraw[m] < mykey) ? 1 : 0;
        skey[r] = (unsigned)(mykey >> 6);
        skid[r] = tid;
        if (r == 0) s_minv = sz[tid];
    }
    __syncthreads();

    // ---- Prefix scan of sorted local indices + Sp (double) ----
    if (tid < JT) {
        int x = skid[tid];
        #pragma unroll
        for (int off = 1; off < 32; off <<= 1) {
            int y = __shfl_up_sync(0xffffffffu, x, off);
            if ((tid & 31) >= off) x += y;
        }
        if (tid == 31) s_w0 = x;
        // Sp partial (original order, any order works for a sum).
        double ds = (double)sz[tid];
        #pragma unroll
        for (int off = 16; off > 0; off >>= 1)
            ds += __shfl_down_sync(0xffffffffu, ds, off);
        if ((tid & 31) == 0) s_sp[tid >> 5] = ds;
        pre[JT] = 0;  // placeholder; rewritten below for tid path
        // stash inclusive scan in register via shared after barrier
        skid[tid] = x;  // reuse skid to carry inclusive partial (skid no longer needed)
    }
    __syncthreads();
    if (tid < JT) {
        int x = skid[tid];
        if (tid >= 32) x += s_w0;
        pre[tid + 1] = x;
        if (tid == 0) pre[0] = 0;
    }
    __syncthreads();

    const double Sp   = s_sp[0] + s_sp[1];
    const float  minv = s_minv;

    // ---- Main: per-row fast (binary search) or slow (exact) ----
    double acc = 0.0;
    #pragma unroll
    for (int r = 0; r < RPT; ++r) {
        const int   gi  = gis[r];
        const float pi  = pis[r];
        const int   rel = gi - gj0;
        if (gi >= n || rel < 0) continue;

        const int drow = rel - (JT - 1);
        const bool rowfast = fulltile && (drow >= 1) &&
                             ((pi - minv) < 0.99f * c02 * (float)drow);
        if (rowfast) {
            const unsigned upi = fkey(pi);
            int pos = 0;
            if (skey[pos + 31] <= upi) pos += 32;
            if (skey[pos + 15] <= upi) pos += 16;
            if (skey[pos +  7] <= upi) pos += 8;
            if (skey[pos +  3] <= upi) pos += 4;
            if (skey[pos +  1] <= upi) pos += 2;
            if (skey[pos     ] <= upi) pos += 1;
            const int C = pos;
            const int S = pre[pos];
            // sum over counted j of (i-j) = rel*C - S  (exact int, < 2^24)
            float term = c02 * (float)(rel * C - S);
            acc += (double)term - ((double)JT * (double)pi - Sp);
        } else {
            // Exact reference op sequence.
            const float gif = (float)gi;
            const float P1  = c02 * gif - pi;
            const float P2  = pi - step * gif;
            const int jend = min(rel, JT - 1);
            for (int jj = 0; jj <= jend; ++jj) {
                float t1 = P1 + sx[jj];
                float t2 = P2 + sy[jj];
                float u  = sz[jj] - pi;
                acc += (double)sel_loss(t1, t2, u);
            }
        }
    }

    // ---- Block reduction in double ----
    double v = acc;
    #pragma unroll
    for (int off = 16; off > 0; off >>= 1)
        v += __shfl_down_sync(0xffffffffu, v, off);
    if ((tid & 31) == 0) wsum[tid >> 5] = v;
    __syncthreads();
    if (tid < 32) {
        v = (tid < (NTHR / 32)) ? wsum[tid] : 0.0;
        #pragma unroll
        for (int off = 2; off > 0; off >>= 1)
            v += __shfl_down_sync(0xffffffffu, v, off);
        if (tid == 0) {
            g_partials[blockIdx.x] = v;
            __threadfence();
            unsigned int ticket = atomicAdd(&g_ticket, 1u);
            is_last = (ticket == (unsigned int)(nblocks - 1));
        }
    }
    __syncthreads();

    // ---- Last block: final reduce, write output, reset ticket ----
    if (is_last) {
        __threadfence();
        double s = 0.0;
        for (int i = tid; i < nblocks; i += NTHR)
            s += g_partials[i];
        #pragma unroll
        for (int off = 16; off > 0; off >>= 1)
            s += __shfl_down_sync(0xffffffffu, s, off);
        if ((tid & 31) == 0) wsum[tid >> 5] = s;
        __syncthreads();
        if (tid == 0) {
            double tot = 0.0;
            #pragma unroll
            for (int w = 0; w < NTHR / 32; ++w) tot += wsum[w];
            double nn = (double)n * (double)n;
            out[0] = (float)(tot / nn);
            g_ticket = 0;   // reset for next graph replay
        }
    }
}

extern "C" void kernel_launch(void* const* d_in, const int* in_sizes, int n_in,
                              void* d_out, int out_size) {
    const float* p   = (const float*)d_in[0];
    const float* z   = (const float*)d_in[1];
    const float* nth = (const float*)d_in[2];
    float* out = (float*)d_out;
    int n = in_sizes[0];

    int nti = (n + IT - 1) / IT;
    int nblocks = 4 * nti * (nti + 1);    // sum over ti of 8*(ti+1); n=8192 -> 1088
    if (nblocks > MAXB) nblocks = MAXB;

    dl_fused_kernel<<<nblocks, NTHR>>>(p, z, nth, out, n, nblocks);
}

// round 8
// speedup vs baseline: 2.3333x; 2.3333x over previous
#include <cuda_runtime.h>
#include <cuda_bf16.h>

#define JT    128   // j-tile width
#define IT    256   // i-tile height (2 rows per thread)
#define NTHR  128
#define MAXB  4096

__device__ double        g_partials[MAXB];
__device__ unsigned int  g_ticket = 0;

typedef unsigned long long u64;

__device__ __forceinline__ u64 pack2(float lo, float hi) {
    u64 r; asm("mov.b64 %0, {%1, %2};" : "=l"(r) : "f"(lo), "f"(hi)); return r;
}
__device__ __forceinline__ void unpack2(u64 v, float& lo, float& hi) {
    asm("mov.b64 {%0, %1}, %2;" : "=f"(lo), "=f"(hi) : "l"(v));
}
__device__ __forceinline__ u64 add2(u64 a, u64 b) {
    u64 r; asm("add.rn.f32x2 %0, %1, %2;" : "=l"(r) : "l"(a), "l"(b)); return r;
}

// Exact per-pair loss: t1 = 0.2s - d, t2 = d - s, u = -d.
// r = (u > 0) ? u : max(max(t1,t2),0)  ==  max((u>0 ? u : max(t1,t2)), 0)
__device__ __forceinline__ float sel_loss(float t1, float t2, float u) {
    float mm = fmaxf(t1, t2);
    float s  = (u > 0.0f) ? u : mm;
    return fmaxf(s, 0.0f);
}

__global__ void __launch_bounds__(NTHR, 8)
dl_fused_kernel(const float* __restrict__ p,
                const float* __restrict__ z_spacing,
                const float* __restrict__ nth_slice,
                float* __restrict__ out,
                int n, int nblocks) {
    // Pre-packed shared: qxy64[j] = pack(x_j, y_j); qzf[j] = p_j (read as u64 pairs).
    __shared__ __align__(16) u64   qxy64[JT];
    __shared__ __align__(8)  float qzf[JT];
    __shared__ double wsum[NTHR / 32];
    __shared__ bool   is_last;

    const int tid = threadIdx.x;

    // Decode (ti, tj): per-ti j-tile count = 2*(ti+1), start(ti) = ti*(ti+1).
    int t  = blockIdx.x;
    int ti = (int)((sqrtf(4.0f * (float)t + 1.0f) - 1.0f) * 0.5f);
    while ((ti + 1) * (ti + 2) <= t) ti++;
    while (ti * (ti + 1) > t) ti--;
    const int tj = t - ti * (ti + 1);

    const float step = z_spacing[0] * nth_slice[0];   // STEP == 1.0
    const float c02  = 0.2f * step;

    const int gj0 = tj * JT;
    const int gi0 = ti * IT + tid;   // row A
    const int gi1 = gi0 + NTHR;      // row B

    // Stage j-tile: one j per thread (JT == NTHR), pre-packed.
    {
        int j = gj0 + tid;
        float pv = (j < n) ? p[j] : 0.0f;
        float jf = (float)j;
        qxy64[tid] = pack2(pv - c02 * jf, step * jf - pv);  // (x, y)
        qzf[tid]   = pv;
    }

    const bool  v0 = (gi0 < n), v1 = (gi1 < n);
    const float pi0 = v0 ? p[gi0] : 0.0f;
    const float pi1 = v1 ? p[gi1] : 0.0f;
    const float gf0 = (float)gi0, gf1 = (float)gi1;
    const u64 P12_0 = pack2(c02 * gf0 - pi0, pi0 - step * gf0);
    const u64 P12_1 = pack2(c02 * gf1 - pi1, pi1 - step * gf1);
    const u64 NPI0  = pack2(-pi0, -pi0);
    const u64 NPI1  = pack2(-pi1, -pi1);

    __syncthreads();

    const bool fullj = (gj0 + JT <= n);
    const int  rel0  = v0 ? (gi0 - gj0) : -1;
    const int  rel1  = v1 ? (gi1 - gj0) : -1;

    float a0 = 0.0f, a1 = 0.0f, b0 = 0.0f, b1 = 0.0f;

    if (fullj && rel0 >= JT - 1 && rel1 >= JT - 1) {
        // Hot path: both rows consume the full j-tile. Loads arrive pre-packed.
        const ulonglong2* qxyv = (const ulonglong2*)qxy64;
        const u64*        qzv  = (const u64*)qzf;
        #pragma unroll 8
        for (int k = 0; k < JT / 2; ++k) {
            ulonglong2 ab = qxyv[k];   // LDS.128: (x0,y0),(x1,y1)
            u64        zz = qzv[k];    // LDS.64 : (pj0, pj1)
            {   // row A
                u64 tA = add2(P12_0, ab.x), tB = add2(P12_0, ab.y), uu = add2(NPI0, zz);
                float t1, t2, t3, t4, u0, u1;
                unpack2(tA, t1, t2); unpack2(tB, t3, t4); unpack2(uu, u0, u1);
                a0 += sel_loss(t1, t2, u0);
                a1 += sel_loss(t3, t4, u1);
            }
            {   // row B
                u64 tA = add2(P12_1, ab.x), tB = add2(P12_1, ab.y), uu = add2(NPI1, zz);
                float t1, t2, t3, t4, u0, u1;
                unpack2(tA, t1, t2); unpack2(tB, t3, t4); unpack2(uu, u0, u1);
                b0 += sel_loss(t1, t2, u0);
                b1 += sel_loss(t3, t4, u1);
            }
        }
    } else {
        // Boundary/diagonal path: per-row, exact scalar ops over valid j only.
        const float* fx = (const float*)qxy64;   // fx[2j] = x_j, fx[2j+1] = y_j
        const int jlim = fullj ? JT : max(0, n - gj0);
        if (rel0 >= 0) {
            const float P1 = c02 * gf0 - pi0, P2 = pi0 - step * gf0;
            const int jend = min(rel0, jlim - 1);
            for (int jj = 0; jj <= jend; ++jj) {
                float t1 = P1 + fx[2 * jj];
                float t2 = P2 + fx[2 * jj + 1];
                float u  = qzf[jj] - pi0;
                a0 += sel_loss(t1, t2, u);
            }
        }
        if (rel1 >= 0) {
            const float P1 = c02 * gf1 - pi1, P2 = pi1 - step * gf1;
            const int jend = min(rel1, jlim - 1);
            for (int jj = 0; jj <= jend; ++jj) {
                float t1 = P1 + fx[2 * jj];
                float t2 = P2 + fx[2 * jj + 1];
                float u  = qzf[jj] - pi1;
                b0 += sel_loss(t1, t2, u);
            }
        }
    }

    // Block reduction in double.
    double v = (double)((a0 + a1) + (b0 + b1));
    #pragma unroll
    for (int off = 16; off > 0; off >>= 1)
        v += __shfl_down_sync(0xffffffffu, v, off);
    if ((tid & 31) == 0) wsum[tid >> 5] = v;
    __syncthreads();
    if (tid < 32) {
        v = (tid < (NTHR / 32)) ? wsum[tid] : 0.0;
        #pragma unroll
        for (int off = 2; off > 0; off >>= 1)
            v += __shfl_down_sync(0xffffffffu, v, off);
        if (tid == 0) {
            g_partials[blockIdx.x] = v;
            __threadfence();
            unsigned int ticket = atomicAdd(&g_ticket, 1u);
            is_last = (ticket == (unsigned int)(nblocks - 1));
        }
    }
    __syncthreads();

    // Last block: final reduce, write output, reset ticket.
    if (is_last) {
        __threadfence();
        double s = 0.0;
        for (int i = tid; i < nblocks; i += NTHR)
            s += g_partials[i];
        #pragma unroll
        for (int off = 16; off > 0; off >>= 1)
            s += __shfl_down_sync(0xffffffffu, s, off);
        if ((tid & 31) == 0) wsum[tid >> 5] = s;
        __syncthreads();
        if (tid == 0) {
            double tot = 0.0;
            #pragma unroll
            for (int w = 0; w < NTHR / 32; ++w) tot += wsum[w];
            double nn = (double)n * (double)n;
            out[0] = (float)(tot / nn);
            g_ticket = 0;   // reset for next graph replay
        }
    }
}

extern "C" void kernel_launch(void* const* d_in, const int* in_sizes, int n_in,
                              void* d_out, int out_size) {
    const float* p   = (const float*)d_in[0];
    const float* z   = (const float*)d_in[1];
    const float* nth = (const float*)d_in[2];
    float* out = (float*)d_out;
    int n = in_sizes[0];

    int nti = (n + IT - 1) / IT;
    int nblocks = nti * (nti + 1);   // sum over ti of 2*(ti+1); n=8192 -> 1056
    if (nblocks > MAXB) nblocks = MAXB;

    dl_fused_kernel<<<nblocks, NTHR>>>(p, z, nth, out, n, nblocks);
}